// round 15
// baseline (speedup 1.0000x reference)
#include <cuda_runtime.h>
#include <cstdint>

#define TABLE_ROWS 1025
#define HIDDEN     128
#define SEQ        512
#define BATCH      2
#define MAXSEQ     512
#define R_MAX      64      // max contiguous table rows cached per table per tile

// Scratch for the projected tables (allocation-free rule: device globals).
__device__ float g_Ass[TABLE_ROWS * HIDDEN];   // pe_ss @ W[:, :128]^T + bias
__device__ float g_Aee[TABLE_ROWS * HIDDEN];   // pe_ee @ W[:, 128:]^T

// ---------------------------------------------------------------------------
// Kernel 1 — EXACT R1 config (measured best of all k1 variants):
// grid (129,2), block 128, 8 rows/block.
// ---------------------------------------------------------------------------
__global__ void __launch_bounds__(128)
project_tables_kernel(const float* __restrict__ pe_ss,
                      const float* __restrict__ pe_ee,
                      const float* __restrict__ W,
                      const float* __restrict__ bias)
{
    const int sel = blockIdx.y;            // 0 -> ss(+bias), 1 -> ee
    const int t0  = blockIdx.x * 8;
    const int h   = threadIdx.x;           // 0..127

    const float* __restrict__ pe = sel ? pe_ee : pe_ss;
    float* __restrict__ outA     = sel ? g_Aee : g_Ass;

    __shared__ float pe_sm[8][HIDDEN];

    #pragma unroll
    for (int r = 0; r < 8; r++) {
        int t = t0 + r;
        pe_sm[r][h] = (t < TABLE_ROWS) ? pe[(size_t)t * HIDDEN + h] : 0.0f;
    }
    __syncthreads();

    float acc[8];
    const float binit = sel ? 0.0f : bias[h];
    #pragma unroll
    for (int r = 0; r < 8; r++) acc[r] = binit;

    const float4* __restrict__ W4 =
        reinterpret_cast<const float4*>(W + (size_t)h * (2 * HIDDEN) + sel * HIDDEN);

    #pragma unroll 8
    for (int kg = 0; kg < HIDDEN / 4; kg++) {
        const float4 w = W4[kg];
        #pragma unroll
        for (int r = 0; r < 8; r++) {
            const float4 p = reinterpret_cast<const float4*>(pe_sm[r])[kg]; // broadcast
            acc[r] += w.x * p.x + w.y * p.y + w.z * p.z + w.w * p.w;
        }
    }

    #pragma unroll
    for (int r = 0; r < 8; r++) {
        int t = t0 + r;
        if (t < TABLE_ROWS) outA[(size_t)t * HIDDEN + h] = acc[r];
    }
}

// ---------------------------------------------------------------------------
// Helpers for kernel 2
// ---------------------------------------------------------------------------
__device__ __forceinline__ void cp_async16(uint32_t saddr, const void* gaddr)
{
    asm volatile("cp.async.cg.shared.global [%0], [%1], 16;"
                 :: "r"(saddr), "l"(gaddr) : "memory");
}

// Predicated LDS.128: load only if row != prev (warp-uniform condition);
// otherwise keep the previous value already in the registers.
__device__ __forceinline__ void lds_if(float4& v, uint32_t saddr, int row, int prev)
{
    asm volatile(
        "{\n\t.reg .pred p;\n\t"
        "setp.ne.s32 p, %4, %5;\n\t"
        "@p ld.shared.v4.f32 {%0, %1, %2, %3}, [%6];\n\t}"
        : "+f"(v.x), "+f"(v.y), "+f"(v.z), "+f"(v.w)
        : "r"(row), "r"(prev), "r"(saddr));
}

// ---------------------------------------------------------------------------
// Kernel 2 — R6 body widened to 16i x 32j tiles (1024 blocks):
// per-block copy (~49 rows) now amortizes over 256 KB of output instead of
// 128 KB -> read amplification 26% -> ~10%, and per-tile prologue/sync costs
// halve. All measured-best elements kept: unrolled loops, no reg cap
// (occupancy proven irrelevant at 34-54%), lds_if dedup, cp.async, PDL.
// ---------------------------------------------------------------------------
__global__ void __launch_bounds__(256)
fuse_gather_tiled(const int* __restrict__ pos_s,
                  const int* __restrict__ pos_e,
                  float* __restrict__ out)
{
    const int b  = blockIdx.z;
    const int i0 = blockIdx.y * 16;
    const int j0 = blockIdx.x * 32;

    __shared__ float4 sA[R_MAX * 32];       // 32 KB
    __shared__ float4 sE[R_MAX * 32];       // 32 KB
    __shared__ int s_psi[16], s_pei[16];
    __shared__ int s_psj[32], s_pej[32];
    __shared__ int s_meta[4];               // loA, nA(0=fallback), loE, nE

    const int tid = threadIdx.x;

    // Prologue — independent of kernel 1, overlaps it under PDL.
    if (tid < 16) {
        s_psi[tid] = pos_s[b * SEQ + i0 + tid];
        s_pei[tid] = pos_e[b * SEQ + i0 + tid];
    }
    if (tid < 32) {
        s_psj[tid] = pos_s[b * SEQ + j0 + tid];
        s_pej[tid] = pos_e[b * SEQ + j0 + tid];
    }
    __syncthreads();

    if (tid == 0) {
        int lo = s_psi[0]  - s_psj[31] + MAXSEQ;   // sorted: endpoints = extrema
        int n  = (s_psi[15] - s_psj[0] + MAXSEQ) - lo + 1;
        s_meta[0] = lo;
        s_meta[1] = (n <= R_MAX) ? n : 0;
        lo = s_pei[0]  - s_pej[31] + MAXSEQ;
        n  = (s_pei[15] - s_pej[0] + MAXSEQ) - lo + 1;
        s_meta[2] = lo;
        s_meta[3] = (n <= R_MAX) ? n : 0;
    }
    __syncthreads();

    // Hardware wait for kernel 1 completion (tables published).
    cudaGridDependencySynchronize();

    const int loA = s_meta[0], nA = s_meta[1];
    const int loE = s_meta[2], nE = s_meta[3];

    const float4* __restrict__ gA = reinterpret_cast<const float4*>(g_Ass);
    const float4* __restrict__ gE = reinterpret_cast<const float4*>(g_Aee);

    const uint32_t sA_base = (uint32_t)__cvta_generic_to_shared(sA);
    const uint32_t sE_base = (uint32_t)__cvta_generic_to_shared(sE);

    const int warp = tid >> 5;
    const int lane = tid & 31;

    if (nA && nE) {
        for (int t = tid; t < nA * 32; t += 256)
            cp_async16(sA_base + t * 16, gA + loA * 32 + t);
        for (int t = tid; t < nE * 32; t += 256)
            cp_async16(sE_base + t * 16, gE + loE * 32 + t);
        asm volatile("cp.async.commit_group;\ncp.async.wait_group 0;" ::: "memory");
        __syncthreads();

        #pragma unroll
        for (int half = 0; half < 2; half++) {
            const int ii = warp * 2 + half;
            const int baseA = s_psi[ii] + MAXSEQ - loA;   // row = baseA - psj
            const int baseE = s_pei[ii] + MAXSEQ - loE;
            float4* __restrict__ orow = reinterpret_cast<float4*>(out) +
                (((size_t)b * SEQ + (i0 + ii)) * SEQ + j0) * (HIDDEN / 4) + lane;

            int prevA = -1, prevE = -1;
            float4 a = make_float4(0.f, 0.f, 0.f, 0.f);
            float4 e = make_float4(0.f, 0.f, 0.f, 0.f);

            #pragma unroll
            for (int jj = 0; jj < 32; jj++) {
                const int rA = baseA - s_psj[jj];         // warp-uniform
                const int rE = baseE - s_pej[jj];

                lds_if(a, sA_base + (rA * 32 + lane) * 16, rA, prevA);
                lds_if(e, sE_base + (rE * 32 + lane) * 16, rE, prevE);
                prevA = rA;
                prevE = rE;

                float4 r;
                r.x = fmaxf(a.x + e.x, 0.0f);
                r.y = fmaxf(a.y + e.y, 0.0f);
                r.z = fmaxf(a.z + e.z, 0.0f);
                r.w = fmaxf(a.w + e.w, 0.0f);

                orow[jj * (HIDDEN / 4)] = r;
            }
        }
    } else {
        // Cold path: range too wide for SMEM — direct global gathers.
        #pragma unroll
        for (int half = 0; half < 2; half++) {
            const int ii  = warp * 2 + half;
            const int psi = s_psi[ii];
            const int pei = s_pei[ii];
            float4* __restrict__ orow = reinterpret_cast<float4*>(out) +
                (((size_t)b * SEQ + (i0 + ii)) * SEQ + j0) * (HIDDEN / 4) + lane;

            for (int jj = 0; jj < 32; jj++) {
                const int iss = psi - s_psj[jj] + MAXSEQ;
                const int iee = pei - s_pej[jj] + MAXSEQ;
                const float4 a = __ldg(gA + iss * 32 + lane);
                const float4 e = __ldg(gE + iee * 32 + lane);
                float4 r;
                r.x = fmaxf(a.x + e.x, 0.0f);
                r.y = fmaxf(a.y + e.y, 0.0f);
                r.z = fmaxf(a.z + e.z, 0.0f);
                r.w = fmaxf(a.w + e.w, 0.0f);
                orow[jj * (HIDDEN / 4)] = r;
            }
        }
    }
}

// ---------------------------------------------------------------------------
// Inputs (metadata order): 0 pos_s [B,S] i32, 1 pos_e [B,S] i32,
// 2 pe_ss [1025,128] f32, 3 pe_se (unused), 4 pe_es (unused),
// 5 pe_ee [1025,128] f32, 6 W [128,256] f32, 7 b [128] f32.
// Output: [B,S,S,H] f32.
// ---------------------------------------------------------------------------
extern "C" void kernel_launch(void* const* d_in, const int* in_sizes, int n_in,
                              void* d_out, int out_size)
{
    const int*   pos_s = (const int*)d_in[0];
    const int*   pos_e = (const int*)d_in[1];
    const float* pe_ss = (const float*)d_in[2];
    const float* pe_ee = (const float*)d_in[5];
    const float* W     = (const float*)d_in[6];
    const float* bias  = (const float*)d_in[7];
    float*       out   = (float*)d_out;

    dim3 grid1((TABLE_ROWS + 7) / 8, 2);
    project_tables_kernel<<<grid1, 128>>>(pe_ss, pe_ee, W, bias);

    // Gather with programmatic dependent launch: prologue overlaps kernel 1.
    cudaLaunchConfig_t cfg = {};
    cfg.gridDim  = dim3(SEQ / 32, SEQ / 16, BATCH);   // 1024 blocks
    cfg.blockDim = dim3(256, 1, 1);
    cfg.stream   = 0;                        // legacy default (same as <<<>>>)
    cudaLaunchAttribute attrs[1];
    attrs[0].id = cudaLaunchAttributeProgrammaticStreamSerialization;
    attrs[0].val.programmaticStreamSerializationAllowed = 1;
    cfg.attrs    = attrs;
    cfg.numAttrs = 1;
    cudaLaunchKernelEx(&cfg, fuse_gather_tiled, pos_s, pos_e, (float*)d_out);
}

// round 16
// speedup vs baseline: 1.0647x; 1.0647x over previous
#include <cuda_runtime.h>
#include <cstdint>

#define TABLE_ROWS 1025
#define HIDDEN     128
#define SEQ        512
#define BATCH      2
#define MAXSEQ     512
#define R_MAX      44      // max contiguous table rows cached per table per tile

// Scratch for the projected tables (allocation-free rule: device globals).
__device__ float g_Ass[TABLE_ROWS * HIDDEN];   // pe_ss @ W[:, :128]^T + bias
__device__ float g_Aee[TABLE_ROWS * HIDDEN];   // pe_ee @ W[:, 128:]^T

// ---------------------------------------------------------------------------
// Kernel 1 — EXACT R1 config (measured best of all k1 variants) + PDL
// trigger: each block signals programmatic-launch-completion at entry so the
// dependent gather grid may launch and run its prologue concurrently.
// (Without the trigger, PDL degenerates to normal serialization — which is
// what R12-R15 unknowingly measured.)
// ---------------------------------------------------------------------------
__global__ void __launch_bounds__(128)
project_tables_kernel(const float* __restrict__ pe_ss,
                      const float* __restrict__ pe_ee,
                      const float* __restrict__ W,
                      const float* __restrict__ bias)
{
    cudaTriggerProgrammaticLaunchCompletion();

    const int sel = blockIdx.y;            // 0 -> ss(+bias), 1 -> ee
    const int t0  = blockIdx.x * 8;
    const int h   = threadIdx.x;           // 0..127

    const float* __restrict__ pe = sel ? pe_ee : pe_ss;
    float* __restrict__ outA     = sel ? g_Aee : g_Ass;

    __shared__ float pe_sm[8][HIDDEN];

    #pragma unroll
    for (int r = 0; r < 8; r++) {
        int t = t0 + r;
        pe_sm[r][h] = (t < TABLE_ROWS) ? pe[(size_t)t * HIDDEN + h] : 0.0f;
    }
    __syncthreads();

    float acc[8];
    const float binit = sel ? 0.0f : bias[h];
    #pragma unroll
    for (int r = 0; r < 8; r++) acc[r] = binit;

    const float4* __restrict__ W4 =
        reinterpret_cast<const float4*>(W + (size_t)h * (2 * HIDDEN) + sel * HIDDEN);

    #pragma unroll 8
    for (int kg = 0; kg < HIDDEN / 4; kg++) {
        const float4 w = W4[kg];
        #pragma unroll
        for (int r = 0; r < 8; r++) {
            const float4 p = reinterpret_cast<const float4*>(pe_sm[r])[kg]; // broadcast
            acc[r] += w.x * p.x + w.y * p.y + w.z * p.z + w.w * p.w;
        }
    }

    #pragma unroll
    for (int r = 0; r < 8; r++) {
        int t = t0 + r;
        if (t < TABLE_ROWS) outA[(size_t)t * HIDDEN + h] = acc[r];
    }
}

// ---------------------------------------------------------------------------
// Helpers for kernel 2
// ---------------------------------------------------------------------------
__device__ __forceinline__ void cp_async16(uint32_t saddr, const void* gaddr)
{
    asm volatile("cp.async.cg.shared.global [%0], [%1], 16;"
                 :: "r"(saddr), "l"(gaddr) : "memory");
}

// Predicated LDS.128: load only if row != prev (warp-uniform condition);
// otherwise keep the previous value already in the registers.
__device__ __forceinline__ void lds_if(float4& v, uint32_t saddr, int row, int prev)
{
    asm volatile(
        "{\n\t.reg .pred p;\n\t"
        "setp.ne.s32 p, %4, %5;\n\t"
        "@p ld.shared.v4.f32 {%0, %1, %2, %3}, [%6];\n\t}"
        : "+f"(v.x), "+f"(v.y), "+f"(v.z), "+f"(v.w)
        : "r"(row), "r"(prev), "r"(saddr));
}

// ---------------------------------------------------------------------------
// Kernel 2 — EXACT R13 body (measured best: gather 42.75 us, 16x16 tiles,
// unrolled, no reg cap, lds_if dedup, cp.async copy). Prologue overlaps
// kernel 1 under PDL; cudaGridDependencySynchronize() gates table reads.
// ---------------------------------------------------------------------------
__global__ void __launch_bounds__(256)
fuse_gather_tiled(const int* __restrict__ pos_s,
                  const int* __restrict__ pos_e,
                  float* __restrict__ out)
{
    const int b  = blockIdx.z;
    const int i0 = blockIdx.y * 16;
    const int j0 = blockIdx.x * 16;

    __shared__ float4 sA[R_MAX * 32];       // 22.5 KB
    __shared__ float4 sE[R_MAX * 32];       // 22.5 KB
    __shared__ int s_psi[16], s_pei[16], s_psj[16], s_pej[16];
    __shared__ int s_meta[4];               // loA, nA(0=fallback), loE, nE

    const int tid = threadIdx.x;

    // Prologue — independent of kernel 1, overlaps it under PDL.
    if (tid < 16) {
        s_psi[tid] = pos_s[b * SEQ + i0 + tid];
        s_pei[tid] = pos_e[b * SEQ + i0 + tid];
        s_psj[tid] = pos_s[b * SEQ + j0 + tid];
        s_pej[tid] = pos_e[b * SEQ + j0 + tid];
    }
    __syncthreads();

    if (tid == 0) {
        int lo = s_psi[0]  - s_psj[15] + MAXSEQ;   // sorted: endpoints = extrema
        int n  = (s_psi[15] - s_psj[0] + MAXSEQ) - lo + 1;
        s_meta[0] = lo;
        s_meta[1] = (n <= R_MAX) ? n : 0;
        lo = s_pei[0]  - s_pej[15] + MAXSEQ;
        n  = (s_pei[15] - s_pej[0] + MAXSEQ) - lo + 1;
        s_meta[2] = lo;
        s_meta[3] = (n <= R_MAX) ? n : 0;
    }
    __syncthreads();

    // Hardware wait for kernel 1 completion (tables published).
    cudaGridDependencySynchronize();

    const int loA = s_meta[0], nA = s_meta[1];
    const int loE = s_meta[2], nE = s_meta[3];

    const float4* __restrict__ gA = reinterpret_cast<const float4*>(g_Ass);
    const float4* __restrict__ gE = reinterpret_cast<const float4*>(g_Aee);

    const uint32_t sA_base = (uint32_t)__cvta_generic_to_shared(sA);
    const uint32_t sE_base = (uint32_t)__cvta_generic_to_shared(sE);

    const int warp = tid >> 5;
    const int lane = tid & 31;

    if (nA && nE) {
        for (int t = tid; t < nA * 32; t += 256)
            cp_async16(sA_base + t * 16, gA + loA * 32 + t);
        for (int t = tid; t < nE * 32; t += 256)
            cp_async16(sE_base + t * 16, gE + loE * 32 + t);
        asm volatile("cp.async.commit_group;\ncp.async.wait_group 0;" ::: "memory");
        __syncthreads();

        #pragma unroll
        for (int half = 0; half < 2; half++) {
            const int ii = warp * 2 + half;
            const int baseA = s_psi[ii] + MAXSEQ - loA;   // row = baseA - psj
            const int baseE = s_pei[ii] + MAXSEQ - loE;
            float4* __restrict__ orow = reinterpret_cast<float4*>(out) +
                (((size_t)b * SEQ + (i0 + ii)) * SEQ + j0) * (HIDDEN / 4) + lane;

            int prevA = -1, prevE = -1;
            float4 a = make_float4(0.f, 0.f, 0.f, 0.f);
            float4 e = make_float4(0.f, 0.f, 0.f, 0.f);

            #pragma unroll
            for (int jj = 0; jj < 16; jj++) {
                const int rA = baseA - s_psj[jj];         // warp-uniform
                const int rE = baseE - s_pej[jj];

                lds_if(a, sA_base + (rA * 32 + lane) * 16, rA, prevA);
                lds_if(e, sE_base + (rE * 32 + lane) * 16, rE, prevE);
                prevA = rA;
                prevE = rE;

                float4 r;
                r.x = fmaxf(a.x + e.x, 0.0f);
                r.y = fmaxf(a.y + e.y, 0.0f);
                r.z = fmaxf(a.z + e.z, 0.0f);
                r.w = fmaxf(a.w + e.w, 0.0f);

                orow[jj * (HIDDEN / 4)] = r;
            }
        }
    } else {
        // Cold path: range too wide for SMEM — direct global gathers.
        #pragma unroll
        for (int half = 0; half < 2; half++) {
            const int ii  = warp * 2 + half;
            const int psi = s_psi[ii];
            const int pei = s_pei[ii];
            float4* __restrict__ orow = reinterpret_cast<float4*>(out) +
                (((size_t)b * SEQ + (i0 + ii)) * SEQ + j0) * (HIDDEN / 4) + lane;

            for (int jj = 0; jj < 16; jj++) {
                const int iss = psi - s_psj[jj] + MAXSEQ;
                const int iee = pei - s_pej[jj] + MAXSEQ;
                const float4 a = __ldg(gA + iss * 32 + lane);
                const float4 e = __ldg(gE + iee * 32 + lane);
                float4 r;
                r.x = fmaxf(a.x + e.x, 0.0f);
                r.y = fmaxf(a.y + e.y, 0.0f);
                r.z = fmaxf(a.z + e.z, 0.0f);
                r.w = fmaxf(a.w + e.w, 0.0f);
                orow[jj * (HIDDEN / 4)] = r;
            }
        }
    }
}

// ---------------------------------------------------------------------------
// Inputs (metadata order): 0 pos_s [B,S] i32, 1 pos_e [B,S] i32,
// 2 pe_ss [1025,128] f32, 3 pe_se (unused), 4 pe_es (unused),
// 5 pe_ee [1025,128] f32, 6 W [128,256] f32, 7 b [128] f32.
// Output: [B,S,S,H] f32.
// ---------------------------------------------------------------------------
extern "C" void kernel_launch(void* const* d_in, const int* in_sizes, int n_in,
                              void* d_out, int out_size)
{
    const int*   pos_s = (const int*)d_in[0];
    const int*   pos_e = (const int*)d_in[1];
    const float* pe_ss = (const float*)d_in[2];
    const float* pe_ee = (const float*)d_in[5];
    const float* W     = (const float*)d_in[6];
    const float* bias  = (const float*)d_in[7];
    float*       out   = (float*)d_out;

    dim3 grid1((TABLE_ROWS + 7) / 8, 2);
    project_tables_kernel<<<grid1, 128>>>(pe_ss, pe_ee, W, bias);

    // Gather with programmatic dependent launch: now that kernel 1 triggers
    // programmatic completion, this grid launches while kernel 1 runs.
    cudaLaunchConfig_t cfg = {};
    cfg.gridDim  = dim3(SEQ / 16, SEQ / 16, BATCH);
    cfg.blockDim = dim3(256, 1, 1);
    cfg.stream   = 0;                        // legacy default (same as <<<>>>)
    cudaLaunchAttribute attrs[1];
    attrs[0].id = cudaLaunchAttributeProgrammaticStreamSerialization;
    attrs[0].val.programmaticStreamSerializationAllowed = 1;
    cfg.attrs    = attrs;
    cfg.numAttrs = 1;
    cudaLaunchKernelEx(&cfg, fuse_gather_tiled, pos_s, pos_e, (float*)d_out);
}

// round 17
// speedup vs baseline: 1.0899x; 1.0237x over previous
#include <cuda_runtime.h>
#include <cstdint>

#define TABLE_ROWS 1025
#define HIDDEN     128
#define SEQ        512
#define BATCH      2
#define MAXSEQ     512
#define R_MAX      44      // max contiguous table rows cached per table per tile

// Scratch for the projected tables (allocation-free rule: device globals).
__device__ float g_Ass[TABLE_ROWS * HIDDEN];   // pe_ss @ W[:, :128]^T + bias
__device__ float g_Aee[TABLE_ROWS * HIDDEN];   // pe_ee @ W[:, 128:]^T

// ---------------------------------------------------------------------------
// Kernel 1 — EXACT R1 config (measured best of all k1 variants) + PDL trigger.
// ---------------------------------------------------------------------------
__global__ void __launch_bounds__(128)
project_tables_kernel(const float* __restrict__ pe_ss,
                      const float* __restrict__ pe_ee,
                      const float* __restrict__ W,
                      const float* __restrict__ bias)
{
    cudaTriggerProgrammaticLaunchCompletion();

    const int sel = blockIdx.y;            // 0 -> ss(+bias), 1 -> ee
    const int t0  = blockIdx.x * 8;
    const int h   = threadIdx.x;           // 0..127

    const float* __restrict__ pe = sel ? pe_ee : pe_ss;
    float* __restrict__ outA     = sel ? g_Aee : g_Ass;

    __shared__ float pe_sm[8][HIDDEN];

    #pragma unroll
    for (int r = 0; r < 8; r++) {
        int t = t0 + r;
        pe_sm[r][h] = (t < TABLE_ROWS) ? pe[(size_t)t * HIDDEN + h] : 0.0f;
    }
    __syncthreads();

    float acc[8];
    const float binit = sel ? 0.0f : bias[h];
    #pragma unroll
    for (int r = 0; r < 8; r++) acc[r] = binit;

    const float4* __restrict__ W4 =
        reinterpret_cast<const float4*>(W + (size_t)h * (2 * HIDDEN) + sel * HIDDEN);

    #pragma unroll 8
    for (int kg = 0; kg < HIDDEN / 4; kg++) {
        const float4 w = W4[kg];
        #pragma unroll
        for (int r = 0; r < 8; r++) {
            const float4 p = reinterpret_cast<const float4*>(pe_sm[r])[kg]; // broadcast
            acc[r] += w.x * p.x + w.y * p.y + w.z * p.z + w.w * p.w;
        }
    }

    #pragma unroll
    for (int r = 0; r < 8; r++) {
        int t = t0 + r;
        if (t < TABLE_ROWS) outA[(size_t)t * HIDDEN + h] = acc[r];
    }
}

// ---------------------------------------------------------------------------
// Helpers for kernel 2
// ---------------------------------------------------------------------------
__device__ __forceinline__ void cp_async16(uint32_t saddr, const void* gaddr)
{
    asm volatile("cp.async.cg.shared.global [%0], [%1], 16;"
                 :: "r"(saddr), "l"(gaddr) : "memory");
}

// Unconditional LDS.128 into fresh registers (chain breaker).
__device__ __forceinline__ void lds4(float4& v, uint32_t saddr)
{
    asm volatile("ld.shared.v4.f32 {%0, %1, %2, %3}, [%4];"
                 : "=f"(v.x), "=f"(v.y), "=f"(v.z), "=f"(v.w)
                 : "r"(saddr));
}

// Predicated LDS.128: load only if row != prev (warp-uniform condition);
// otherwise keep the previous value already in the registers.
__device__ __forceinline__ void lds_if(float4& v, uint32_t saddr, int row, int prev)
{
    asm volatile(
        "{\n\t.reg .pred p;\n\t"
        "setp.ne.s32 p, %4, %5;\n\t"
        "@p ld.shared.v4.f32 {%0, %1, %2, %3}, [%6];\n\t}"
        : "+f"(v.x), "+f"(v.y), "+f"(v.z), "+f"(v.w)
        : "r"(row), "r"(prev), "r"(saddr));
}

// ---------------------------------------------------------------------------
// Kernel 2 — R13 body with the dedup chain SEGMENTED: the 16-jj loop is
// split into 4 independent groups of 4. Group-leading LDS is unconditional
// (fresh registers), so the serial predicated-LDS chain depth drops 16 -> 4
// and per-warp LDS MLP rises 4x. __launch_bounds__(256,3) caps regs at 85
// (currently 70) so extra live values cannot drop residency below 3 CTA/SM.
// ---------------------------------------------------------------------------
__global__ void __launch_bounds__(256, 3)
fuse_gather_tiled(const int* __restrict__ pos_s,
                  const int* __restrict__ pos_e,
                  float* __restrict__ out)
{
    const int b  = blockIdx.z;
    const int i0 = blockIdx.y * 16;
    const int j0 = blockIdx.x * 16;

    __shared__ float4 sA[R_MAX * 32];       // 22.5 KB
    __shared__ float4 sE[R_MAX * 32];       // 22.5 KB
    __shared__ int s_psi[16], s_pei[16], s_psj[16], s_pej[16];
    __shared__ int s_meta[4];               // loA, nA(0=fallback), loE, nE

    const int tid = threadIdx.x;

    // Prologue — independent of kernel 1, overlaps it under PDL.
    if (tid < 16) {
        s_psi[tid] = pos_s[b * SEQ + i0 + tid];
        s_pei[tid] = pos_e[b * SEQ + i0 + tid];
        s_psj[tid] = pos_s[b * SEQ + j0 + tid];
        s_pej[tid] = pos_e[b * SEQ + j0 + tid];
    }
    __syncthreads();

    if (tid == 0) {
        int lo = s_psi[0]  - s_psj[15] + MAXSEQ;   // sorted: endpoints = extrema
        int n  = (s_psi[15] - s_psj[0] + MAXSEQ) - lo + 1;
        s_meta[0] = lo;
        s_meta[1] = (n <= R_MAX) ? n : 0;
        lo = s_pei[0]  - s_pej[15] + MAXSEQ;
        n  = (s_pei[15] - s_pej[0] + MAXSEQ) - lo + 1;
        s_meta[2] = lo;
        s_meta[3] = (n <= R_MAX) ? n : 0;
    }
    __syncthreads();

    // Hardware wait for kernel 1 completion (tables published).
    cudaGridDependencySynchronize();

    const int loA = s_meta[0], nA = s_meta[1];
    const int loE = s_meta[2], nE = s_meta[3];

    const float4* __restrict__ gA = reinterpret_cast<const float4*>(g_Ass);
    const float4* __restrict__ gE = reinterpret_cast<const float4*>(g_Aee);

    const uint32_t sA_base = (uint32_t)__cvta_generic_to_shared(sA);
    const uint32_t sE_base = (uint32_t)__cvta_generic_to_shared(sE);

    const int warp = tid >> 5;
    const int lane = tid & 31;

    if (nA && nE) {
        for (int t = tid; t < nA * 32; t += 256)
            cp_async16(sA_base + t * 16, gA + loA * 32 + t);
        for (int t = tid; t < nE * 32; t += 256)
            cp_async16(sE_base + t * 16, gE + loE * 32 + t);
        asm volatile("cp.async.commit_group;\ncp.async.wait_group 0;" ::: "memory");
        __syncthreads();

        #pragma unroll
        for (int half = 0; half < 2; half++) {
            const int ii = warp * 2 + half;
            const int baseA = s_psi[ii] + MAXSEQ - loA;   // row = baseA - psj
            const int baseE = s_pei[ii] + MAXSEQ - loE;
            float4* __restrict__ orow = reinterpret_cast<float4*>(out) +
                (((size_t)b * SEQ + (i0 + ii)) * SEQ + j0) * (HIDDEN / 4) + lane;

            #pragma unroll
            for (int g = 0; g < 4; g++) {          // 4 independent groups
                const int jb = g * 4;

                const int rA0 = baseA - s_psj[jb + 0];
                const int rE0 = baseE - s_pej[jb + 0];

                float4 a, e;                        // fresh per group
                lds4(a, sA_base + (rA0 * 32 + lane) * 16);   // chain breaker
                lds4(e, sE_base + (rE0 * 32 + lane) * 16);

                int prevA = rA0, prevE = rE0;

                #pragma unroll
                for (int q = 0; q < 4; q++) {
                    const int jj = jb + q;
                    if (q > 0) {
                        const int rA = baseA - s_psj[jj];    // warp-uniform
                        const int rE = baseE - s_pej[jj];
                        lds_if(a, sA_base + (rA * 32 + lane) * 16, rA, prevA);
                        lds_if(e, sE_base + (rE * 32 + lane) * 16, rE, prevE);
                        prevA = rA;
                        prevE = rE;
                    }

                    float4 r;
                    r.x = fmaxf(a.x + e.x, 0.0f);
                    r.y = fmaxf(a.y + e.y, 0.0f);
                    r.z = fmaxf(a.z + e.z, 0.0f);
                    r.w = fmaxf(a.w + e.w, 0.0f);

                    orow[jj * (HIDDEN / 4)] = r;
                }
            }
        }
    } else {
        // Cold path: range too wide for SMEM — direct global gathers.
        #pragma unroll
        for (int half = 0; half < 2; half++) {
            const int ii  = warp * 2 + half;
            const int psi = s_psi[ii];
            const int pei = s_pei[ii];
            float4* __restrict__ orow = reinterpret_cast<float4*>(out) +
                (((size_t)b * SEQ + (i0 + ii)) * SEQ + j0) * (HIDDEN / 4) + lane;

            for (int jj = 0; jj < 16; jj++) {
                const int iss = psi - s_psj[jj] + MAXSEQ;
                const int iee = pei - s_pej[jj] + MAXSEQ;
                const float4 a = __ldg(gA + iss * 32 + lane);
                const float4 e = __ldg(gE + iee * 32 + lane);
                float4 r;
                r.x = fmaxf(a.x + e.x, 0.0f);
                r.y = fmaxf(a.y + e.y, 0.0f);
                r.z = fmaxf(a.z + e.z, 0.0f);
                r.w = fmaxf(a.w + e.w, 0.0f);
                orow[jj * (HIDDEN / 4)] = r;
            }
        }
    }
}

// ---------------------------------------------------------------------------
// Inputs (metadata order): 0 pos_s [B,S] i32, 1 pos_e [B,S] i32,
// 2 pe_ss [1025,128] f32, 3 pe_se (unused), 4 pe_es (unused),
// 5 pe_ee [1025,128] f32, 6 W [128,256] f32, 7 b [128] f32.
// Output: [B,S,S,H] f32.
// ---------------------------------------------------------------------------
extern "C" void kernel_launch(void* const* d_in, const int* in_sizes, int n_in,
                              void* d_out, int out_size)
{
    const int*   pos_s = (const int*)d_in[0];
    const int*   pos_e = (const int*)d_in[1];
    const float* pe_ss = (const float*)d_in[2];
    const float* pe_ee = (const float*)d_in[5];
    const float* W     = (const float*)d_in[6];
    const float* bias  = (const float*)d_in[7];
    float*       out   = (float*)d_out;

    dim3 grid1((TABLE_ROWS + 7) / 8, 2);
    project_tables_kernel<<<grid1, 128>>>(pe_ss, pe_ee, W, bias);

    // Gather with programmatic dependent launch (neutral but free).
    cudaLaunchConfig_t cfg = {};
    cfg.gridDim  = dim3(SEQ / 16, SEQ / 16, BATCH);
    cfg.blockDim = dim3(256, 1, 1);
    cfg.stream   = 0;                        // legacy default (same as <<<>>>)
    cudaLaunchAttribute attrs[1];
    attrs[0].id = cudaLaunchAttributeProgrammaticStreamSerialization;
    attrs[0].val.programmaticStreamSerializationAllowed = 1;
    cfg.attrs    = attrs;
    cfg.numAttrs = 1;
    cudaLaunchKernelEx(&cfg, fuse_gather_tiled, pos_s, pos_e, (float*)d_out);
}